// round 4
// baseline (speedup 1.0000x reference)
#include <cuda_runtime.h>
#include <cstdint>

#define T_TOK 8192
#define D_DIM 1024
#define E_EXP 8
#define F_DIM 2048
#define NSLOT (2 * T_TOK)

// ---------------- device-global scratch ----------------
__device__ int   g_cnt[E_EXP];
__device__ int   g_list[E_EXP * T_TOK];
__device__ float g_probs[NSLOT];
__device__ float g_H[(size_t)NSLOT * F_DIM];      // tf32-rounded intermediate
__device__ float g_Y[(size_t)NSLOT * D_DIM];
__device__ float g_xr[(size_t)T_TOK * D_DIM];     // tf32-rounded copies
__device__ float g_w1r[(size_t)E_EXP * D_DIM * F_DIM];
__device__ float g_w3r[(size_t)E_EXP * D_DIM * F_DIM];
__device__ float g_w2r[(size_t)E_EXP * F_DIM * D_DIM];

// ---------------- helpers ----------------
__device__ __forceinline__ uint32_t smem_u32(const void* p) {
    uint32_t a;
    asm("{ .reg .u64 t; cvta.to.shared.u64 t, %1; cvt.u32.u64 %0, t; }" : "=r"(a) : "l"(p));
    return a;
}
__device__ __forceinline__ float to_tf32(float x) {
    uint32_t r;
    asm("cvt.rna.tf32.f32 %0, %1;" : "=r"(r) : "f"(x));
    return __uint_as_float(r);
}
#define CP16(dst, src) asm volatile("cp.async.cg.shared.global [%0], [%1], 16;" :: "r"(dst), "l"(src))
#define CP_COMMIT()    asm volatile("cp.async.commit_group;")
#define CP_WAIT1()     asm volatile("cp.async.wait_group 1;")

#define MMA_TF32(c, a, b)                                                          \
    asm volatile("mma.sync.aligned.m16n8k8.row.col.f32.tf32.tf32.f32 "             \
                 "{%0,%1,%2,%3}, {%4,%5,%6,%7}, {%8,%9}, {%0,%1,%2,%3};"           \
                 : "+f"((c)[0]), "+f"((c)[1]), "+f"((c)[2]), "+f"((c)[3])          \
                 : "r"((a)[0]), "r"((a)[1]), "r"((a)[2]), "r"((a)[3]),             \
                   "r"((b)[0]), "r"((b)[1]))

// A smem: rows padded to 36 floats (144B)
#define AST 36
#define A_BYTES (128 * AST * 4)   // 18432

// ---------------- init ----------------
__global__ void init_kernel() {
    if (threadIdx.x < E_EXP) g_cnt[threadIdx.x] = 0;
}

// ---------------- tf32 pre-round: single fused kernel over all 4 tensors ------
__global__ void __launch_bounds__(256) round_all_kernel(const float4* __restrict__ x,
                                                        const float4* __restrict__ w1,
                                                        const float4* __restrict__ w3,
                                                        const float4* __restrict__ w2,
                                                        float4* __restrict__ xr,
                                                        float4* __restrict__ w1r,
                                                        float4* __restrict__ w3r,
                                                        float4* __restrict__ w2r) {
    const int NX = T_TOK * D_DIM / 4;
    const int NW = E_EXP * D_DIM * F_DIM / 4;
    int i = blockIdx.x * 256 + threadIdx.x;
    int stride = gridDim.x * 256;
    for (; i < NX + 3 * NW; i += stride) {
        const float4* src; float4* dst; int j = i;
        if (j < NX)            { src = x;  dst = xr;  }
        else if ((j -= NX) < NW) { src = w1; dst = w1r; }
        else if ((j -= NW) < NW) { src = w3; dst = w3r; }
        else     { j -= NW;      src = w2; dst = w2r; }
        float4 v = src[j];
        v.x = to_tf32(v.x); v.y = to_tf32(v.y);
        v.z = to_tf32(v.z); v.w = to_tf32(v.w);
        dst[j] = v;
    }
}

// ---------------- gating (proven) ----------------
__global__ void __launch_bounds__(256) gate_kernel(const float* __restrict__ x,
                                                   const float* __restrict__ wg) {
    __shared__ float swg[E_EXP][D_DIM];
    int tid = threadIdx.x;
    for (int i = tid; i < D_DIM * E_EXP; i += 256) {
        int d = i >> 3, e = i & 7;
        swg[e][d] = wg[i];
    }
    __syncthreads();

    int warp = tid >> 5, lane = tid & 31;
    int t = blockIdx.x * 8 + warp;
    const float* xr = x + (size_t)t * D_DIM;

    float acc[E_EXP];
#pragma unroll
    for (int e = 0; e < E_EXP; e++) acc[e] = 0.f;
    for (int d = lane; d < D_DIM; d += 32) {
        float xv = xr[d];
#pragma unroll
        for (int e = 0; e < E_EXP; e++) acc[e] = fmaf(xv, swg[e][d], acc[e]);
    }
#pragma unroll
    for (int e = 0; e < E_EXP; e++)
#pragma unroll
        for (int o = 16; o > 0; o >>= 1)
            acc[e] += __shfl_xor_sync(0xffffffffu, acc[e], o);

    if (lane == 0) {
        int e0 = 0; float l0 = acc[0];
#pragma unroll
        for (int e = 1; e < E_EXP; e++) if (acc[e] > l0) { l0 = acc[e]; e0 = e; }
        int e1 = -1; float l1 = -3.0e38f;
#pragma unroll
        for (int e = 0; e < E_EXP; e++) {
            if (e == e0) continue;
            if (acc[e] > l1) { l1 = acc[e]; e1 = e; }
        }
        float ex  = __expf(l1 - l0);
        float inv = 1.f / (1.f + ex);
        g_probs[2 * t]     = inv;
        g_probs[2 * t + 1] = ex * inv;
        int p0 = atomicAdd(&g_cnt[e0], 1);
        g_list[e0 * T_TOK + p0] = 2 * t;
        int p1 = atomicAdd(&g_cnt[e1], 1);
        g_list[e1 * T_TOK + p1] = 2 * t + 1;
    }
}

// ======================= GEMM1: H = silu(x@w1) * (x@w3) =======================
// CTA 128x128, 8 warps (2m x 4n), warp 64x32. A via 3-stage cp.async smem;
// B1/B3 fragments via direct LDG (L1-resident), double-buffered across kk.
__global__ void __launch_bounds__(256, 1) gemm1_kernel(const float* __restrict__ xr,
                                                       const float* __restrict__ w1,
                                                       const float* __restrict__ w3) {
    int e   = blockIdx.z;
    int n_e = g_cnt[e];
    int m0  = blockIdx.x * 128;
    if (m0 >= n_e) return;
    int f0  = blockIdx.y * 128;

    extern __shared__ char smem[];
    int* slots = (int*)smem;
    uint32_t sb = smem_u32(smem);
    int tid = threadIdx.x, wid = tid >> 5, lane = tid & 31;

    if (tid < 128) {
        int m = m0 + tid;
        slots[tid] = g_list[e * T_TOK + (m < n_e ? m : m0)];
    }
    __syncthreads();

    int g = lane >> 2, t = lane & 3;
    int m0w = (wid & 1) * 64, n0w = (wid >> 1) * 32;

    // per-lane B base pointers: row t, col n0w+g (absolute k added per load)
    const float* W1l = w1 + (size_t)e * D_DIM * F_DIM + (size_t)t * F_DIM + f0 + n0w + g;
    const float* W3l = w3 + (size_t)e * D_DIM * F_DIM + (size_t)t * F_DIM + f0 + n0w + g;

    auto issueA = [&](int ci, int s) {
        int k0 = ci * 32;
        uint32_t base = sb + 1024 + s * A_BYTES;
#pragma unroll
        for (int it = 0; it < 4; it++) {
            int idx = it * 256 + tid;
            int row = idx >> 3, kq = idx & 7;
            const float* src = xr + (size_t)(slots[row] >> 1) * D_DIM + k0 + kq * 4;
            CP16(base + row * 144 + kq * 16, src);
        }
        CP_COMMIT();
    };

    uint32_t b1f[2][4][2], b3f[2][4][2];
    auto loadB = [&](int k8, int buf) {          // k8 = absolute k block (multiple of 8)
        const float* p1 = W1l + (size_t)k8 * F_DIM;
        const float* p3 = W3l + (size_t)k8 * F_DIM;
#pragma unroll
        for (int nf = 0; nf < 4; nf++) {
            b1f[buf][nf][0] = __float_as_uint(p1[nf * 8]);
            b1f[buf][nf][1] = __float_as_uint(p1[nf * 8 + 4 * (size_t)F_DIM]);
            b3f[buf][nf][0] = __float_as_uint(p3[nf * 8]);
            b3f[buf][nf][1] = __float_as_uint(p3[nf * 8 + 4 * (size_t)F_DIM]);
        }
    };

    issueA(0, 0);
    issueA(1, 1);
    loadB(0, 0);

    float c1[4][4][4], c3[4][4][4];
#pragma unroll
    for (int a = 0; a < 4; a++)
#pragma unroll
        for (int b = 0; b < 4; b++)
#pragma unroll
            for (int r = 0; r < 4; r++) { c1[a][b][r] = 0.f; c3[a][b][r] = 0.f; }

    const int NCH = D_DIM / 32;  // 32
    int cur = 0, ibuf = 2;
    for (int ci = 0; ci < NCH; ci++) {
        CP_WAIT1();
        __syncthreads();
        if (ci + 2 < NCH) issueA(ci + 2, ibuf); else CP_COMMIT();
        if (++ibuf == 3) ibuf = 0;

        const float* As = (const float*)(smem + 1024 + cur * A_BYTES);
        if (++cur == 3) cur = 0;

#pragma unroll
        for (int kk = 0; kk < 4; kk++) {
            int nk = ci * 4 + kk + 1;                 // next k-block index
            if (nk < NCH * 4) loadB(nk * 8, (kk + 1) & 1);

            uint32_t af[4][4];
#pragma unroll
            for (int mf = 0; mf < 4; mf++) {
                const float* ap = As + (m0w + mf * 16 + g) * AST + kk * 8 + t;
                af[mf][0] = __float_as_uint(ap[0]);
                af[mf][1] = __float_as_uint(ap[8 * AST]);
                af[mf][2] = __float_as_uint(ap[4]);
                af[mf][3] = __float_as_uint(ap[8 * AST + 4]);
            }
            int cb = kk & 1;
#pragma unroll
            for (int mf = 0; mf < 4; mf++)
#pragma unroll
                for (int nf = 0; nf < 4; nf++) {
                    MMA_TF32(c1[mf][nf], af[mf], b1f[cb][nf]);
                    MMA_TF32(c3[mf][nf], af[mf], b3f[cb][nf]);
                }
        }
    }

    // ---- epilogue: H = rna_tf32(silu(c1) * c3) ----
#pragma unroll
    for (int mf = 0; mf < 4; mf++) {
#pragma unroll
        for (int half = 0; half < 2; half++) {
            int row = m0w + mf * 16 + g + 8 * half;
            if (m0 + row >= n_e) continue;
            float* hp = g_H + (size_t)slots[row] * F_DIM + f0;
#pragma unroll
            for (int nf = 0; nf < 4; nf++) {
                float v0 = c1[mf][nf][2 * half + 0];
                float v1 = c1[mf][nf][2 * half + 1];
                float2 o;
                o.x = to_tf32((v0 / (1.f + __expf(-v0))) * c3[mf][nf][2 * half + 0]);
                o.y = to_tf32((v1 / (1.f + __expf(-v1))) * c3[mf][nf][2 * half + 1]);
                *(float2*)(hp + n0w + nf * 8 + 2 * t) = o;
            }
        }
    }
}

// ======================= GEMM2: Y = H @ w2 =======================
// Same structure: A (gathered H rows) via cp.async smem, B via direct LDG.
__global__ void __launch_bounds__(256, 2) gemm2_kernel(const float* __restrict__ w2) {
    int e   = blockIdx.z;
    int n_e = g_cnt[e];
    int m0  = blockIdx.x * 128;
    if (m0 >= n_e) return;
    int n0  = blockIdx.y * 128;

    extern __shared__ char smem[];
    int* slots = (int*)smem;
    uint32_t sb = smem_u32(smem);
    int tid = threadIdx.x, wid = tid >> 5, lane = tid & 31;

    if (tid < 128) {
        int m = m0 + tid;
        slots[tid] = g_list[e * T_TOK + (m < n_e ? m : m0)];
    }
    __syncthreads();

    int g = lane >> 2, t = lane & 3;
    int m0w = (wid & 1) * 64, n0w = (wid >> 1) * 32;

    const float* W2l = w2 + (size_t)e * F_DIM * D_DIM + (size_t)t * D_DIM + n0 + n0w + g;

    auto issueA = [&](int ci, int s) {
        int k0 = ci * 32;
        uint32_t base = sb + 1024 + s * A_BYTES;
#pragma unroll
        for (int it = 0; it < 4; it++) {
            int idx = it * 256 + tid;
            int row = idx >> 3, kq = idx & 7;
            const float* src = g_H + (size_t)slots[row] * F_DIM + k0 + kq * 4;
            CP16(base + row * 144 + kq * 16, src);
        }
        CP_COMMIT();
    };

    uint32_t bf[2][4][2];
    auto loadB = [&](int k8, int buf) {
        const float* p = W2l + (size_t)k8 * D_DIM;
#pragma unroll
        for (int nf = 0; nf < 4; nf++) {
            bf[buf][nf][0] = __float_as_uint(p[nf * 8]);
            bf[buf][nf][1] = __float_as_uint(p[nf * 8 + 4 * (size_t)D_DIM]);
        }
    };

    issueA(0, 0);
    issueA(1, 1);
    loadB(0, 0);

    float c[4][4][4];
#pragma unroll
    for (int a = 0; a < 4; a++)
#pragma unroll
        for (int b = 0; b < 4; b++)
#pragma unroll
            for (int r = 0; r < 4; r++) c[a][b][r] = 0.f;

    const int NCH = F_DIM / 32;  // 64
    int cur = 0, ibuf = 2;
    for (int ci = 0; ci < NCH; ci++) {
        CP_WAIT1();
        __syncthreads();
        if (ci + 2 < NCH) issueA(ci + 2, ibuf); else CP_COMMIT();
        if (++ibuf == 3) ibuf = 0;

        const float* As = (const float*)(smem + 1024 + cur * A_BYTES);
        if (++cur == 3) cur = 0;

#pragma unroll
        for (int kk = 0; kk < 4; kk++) {
            int nk = ci * 4 + kk + 1;
            if (nk < NCH * 4) loadB(nk * 8, (kk + 1) & 1);

            uint32_t af[4][4];
#pragma unroll
            for (int mf = 0; mf < 4; mf++) {
                const float* ap = As + (m0w + mf * 16 + g) * AST + kk * 8 + t;
                af[mf][0] = __float_as_uint(ap[0]);
                af[mf][1] = __float_as_uint(ap[8 * AST]);
                af[mf][2] = __float_as_uint(ap[4]);
                af[mf][3] = __float_as_uint(ap[8 * AST + 4]);
            }
            int cb = kk & 1;
#pragma unroll
            for (int mf = 0; mf < 4; mf++)
#pragma unroll
                for (int nf = 0; nf < 4; nf++)
                    MMA_TF32(c[mf][nf], af[mf], bf[cb][nf]);
        }
    }

#pragma unroll
    for (int mf = 0; mf < 4; mf++) {
#pragma unroll
        for (int half = 0; half < 2; half++) {
            int row = m0w + mf * 16 + g + 8 * half;
            if (m0 + row >= n_e) continue;
            float* yp = g_Y + (size_t)slots[row] * D_DIM + n0;
#pragma unroll
            for (int nf = 0; nf < 4; nf++) {
                float2 o;
                o.x = c[mf][nf][2 * half + 0];
                o.y = c[mf][nf][2 * half + 1];
                *(float2*)(yp + n0w + nf * 8 + 2 * t) = o;
            }
        }
    }
}

// ---------------- combine ----------------
__global__ void __launch_bounds__(256) combine_kernel(float* __restrict__ out) {
    int idx = blockIdx.x * 256 + threadIdx.x;
    int t   = idx / (D_DIM / 4);
    int d4  = idx % (D_DIM / 4);
    float p0 = g_probs[2 * t], p1 = g_probs[2 * t + 1];
    const float4* y0 = (const float4*)(g_Y + (size_t)(2 * t) * D_DIM) + d4;
    const float4* y1 = (const float4*)(g_Y + (size_t)(2 * t + 1) * D_DIM) + d4;
    float4 a = *y0, b = *y1, o;
    o.x = p0 * a.x + p1 * b.x;
    o.y = p0 * a.y + p1 * b.y;
    o.z = p0 * a.z + p1 * b.z;
    o.w = p0 * a.w + p1 * b.w;
    *((float4*)(out + (size_t)t * D_DIM) + d4) = o;
}

// ---------------- launch ----------------
extern "C" void kernel_launch(void* const* d_in, const int* in_sizes, int n_in,
                              void* d_out, int out_size) {
    const float* x  = (const float*)d_in[0];
    const float* wg = (const float*)d_in[1];
    const float* w1 = (const float*)d_in[2];
    const float* w3 = (const float*)d_in[3];
    const float* w2 = (const float*)d_in[4];
    float* out = (float*)d_out;

    const int SMEM_G = 1024 + 3 * A_BYTES;   // 56320
    cudaFuncSetAttribute(gemm1_kernel, cudaFuncAttributeMaxDynamicSharedMemorySize, SMEM_G);
    cudaFuncSetAttribute(gemm2_kernel, cudaFuncAttributeMaxDynamicSharedMemorySize, SMEM_G);

    float *xr, *w1r, *w3r, *w2r;
    cudaGetSymbolAddress((void**)&xr,  g_xr);
    cudaGetSymbolAddress((void**)&w1r, g_w1r);
    cudaGetSymbolAddress((void**)&w3r, g_w3r);
    cudaGetSymbolAddress((void**)&w2r, g_w2r);

    init_kernel<<<1, 32>>>();
    round_all_kernel<<<8192, 256>>>((const float4*)x, (const float4*)w1,
                                    (const float4*)w3, (const float4*)w2,
                                    (float4*)xr, (float4*)w1r, (float4*)w3r, (float4*)w2r);
    gate_kernel<<<T_TOK / 8, 256>>>(x, wg);

    gemm1_kernel<<<dim3(T_TOK / 128, F_DIM / 128, E_EXP), 256, SMEM_G>>>(xr, w1r, w3r);
    gemm2_kernel<<<dim3(T_TOK / 128, D_DIM / 128, E_EXP), 256, SMEM_G>>>(w2r);
    combine_kernel<<<(T_TOK * D_DIM / 4) / 256, 256>>>(out);
}

// round 5
// speedup vs baseline: 1.0002x; 1.0002x over previous
#include <cuda_runtime.h>
#include <cstdint>

#define T_TOK 8192
#define D_DIM 1024
#define E_EXP 8
#define F_DIM 2048
#define NSLOT (2 * T_TOK)

// ---------------- device-global scratch ----------------
__device__ int   g_cnt[E_EXP];
__device__ int   g_list[E_EXP * T_TOK];
__device__ float g_probs[NSLOT];
__device__ float g_H[(size_t)NSLOT * F_DIM];      // tf32-rounded intermediate
__device__ float g_Y[(size_t)NSLOT * D_DIM];
__device__ float g_xr[(size_t)T_TOK * D_DIM];     // tf32-rounded copies
__device__ float g_w1r[(size_t)E_EXP * D_DIM * F_DIM];
__device__ float g_w3r[(size_t)E_EXP * D_DIM * F_DIM];
__device__ float g_w2r[(size_t)E_EXP * F_DIM * D_DIM];

// ---------------- helpers ----------------
__device__ __forceinline__ uint32_t smem_u32(const void* p) {
    uint32_t a;
    asm("{ .reg .u64 t; cvta.to.shared.u64 t, %1; cvt.u32.u64 %0, t; }" : "=r"(a) : "l"(p));
    return a;
}
__device__ __forceinline__ float to_tf32(float x) {
    uint32_t r;
    asm("cvt.rna.tf32.f32 %0, %1;" : "=r"(r) : "f"(x));
    return __uint_as_float(r);
}
#define CP16(dst, src) asm volatile("cp.async.cg.shared.global [%0], [%1], 16;" :: "r"(dst), "l"(src))
#define CP_COMMIT()    asm volatile("cp.async.commit_group;")
#define CP_WAIT1()     asm volatile("cp.async.wait_group 1;")
#define CP_WAIT2()     asm volatile("cp.async.wait_group 2;")

#define MMA_TF32(c, a, b)                                                          \
    asm volatile("mma.sync.aligned.m16n8k8.row.col.f32.tf32.tf32.f32 "             \
                 "{%0,%1,%2,%3}, {%4,%5,%6,%7}, {%8,%9}, {%0,%1,%2,%3};"           \
                 : "+f"((c)[0]), "+f"((c)[1]), "+f"((c)[2]), "+f"((c)[3])          \
                 : "r"((a)[0]), "r"((a)[1]), "r"((a)[2]), "r"((a)[3]),             \
                   "r"((b)[0]), "r"((b)[1]))

// smem strides (floats): A rows padded to 36 (144B), B rows padded to 136 (544B)
#define AST 36
#define BST 136
#define A_BYTES (128 * AST * 4)   // 18432
#define B_BYTES (32 * BST * 4)    // 17408

// ---------------- init ----------------
__global__ void init_kernel() {
    if (threadIdx.x < E_EXP) g_cnt[threadIdx.x] = 0;
}

// ---------------- tf32 pre-round: single fused kernel over all 4 tensors ------
__global__ void __launch_bounds__(256) round_all_kernel(const float4* __restrict__ x,
                                                        const float4* __restrict__ w1,
                                                        const float4* __restrict__ w3,
                                                        const float4* __restrict__ w2,
                                                        float4* __restrict__ xr,
                                                        float4* __restrict__ w1r,
                                                        float4* __restrict__ w3r,
                                                        float4* __restrict__ w2r) {
    const int NX = T_TOK * D_DIM / 4;
    const int NW = E_EXP * D_DIM * F_DIM / 4;
    int i = blockIdx.x * 256 + threadIdx.x;
    int stride = gridDim.x * 256;
    for (; i < NX + 3 * NW; i += stride) {
        const float4* src; float4* dst; int j = i;
        if (j < NX)              { src = x;  dst = xr;  }
        else if ((j -= NX) < NW) { src = w1; dst = w1r; }
        else if ((j -= NW) < NW) { src = w3; dst = w3r; }
        else     { j -= NW;        src = w2; dst = w2r; }
        float4 v = src[j];
        v.x = to_tf32(v.x); v.y = to_tf32(v.y);
        v.z = to_tf32(v.z); v.w = to_tf32(v.w);
        dst[j] = v;
    }
}

// ---------------- gating (proven) ----------------
__global__ void __launch_bounds__(256) gate_kernel(const float* __restrict__ x,
                                                   const float* __restrict__ wg) {
    __shared__ float swg[E_EXP][D_DIM];
    int tid = threadIdx.x;
    for (int i = tid; i < D_DIM * E_EXP; i += 256) {
        int d = i >> 3, e = i & 7;
        swg[e][d] = wg[i];
    }
    __syncthreads();

    int warp = tid >> 5, lane = tid & 31;
    int t = blockIdx.x * 8 + warp;
    const float* xr = x + (size_t)t * D_DIM;

    float acc[E_EXP];
#pragma unroll
    for (int e = 0; e < E_EXP; e++) acc[e] = 0.f;
    for (int d = lane; d < D_DIM; d += 32) {
        float xv = xr[d];
#pragma unroll
        for (int e = 0; e < E_EXP; e++) acc[e] = fmaf(xv, swg[e][d], acc[e]);
    }
#pragma unroll
    for (int e = 0; e < E_EXP; e++)
#pragma unroll
        for (int o = 16; o > 0; o >>= 1)
            acc[e] += __shfl_xor_sync(0xffffffffu, acc[e], o);

    if (lane == 0) {
        int e0 = 0; float l0 = acc[0];
#pragma unroll
        for (int e = 1; e < E_EXP; e++) if (acc[e] > l0) { l0 = acc[e]; e0 = e; }
        int e1 = -1; float l1 = -3.0e38f;
#pragma unroll
        for (int e = 0; e < E_EXP; e++) {
            if (e == e0) continue;
            if (acc[e] > l1) { l1 = acc[e]; e1 = e; }
        }
        float ex  = __expf(l1 - l0);
        float inv = 1.f / (1.f + ex);
        g_probs[2 * t]     = inv;
        g_probs[2 * t + 1] = ex * inv;
        int p0 = atomicAdd(&g_cnt[e0], 1);
        g_list[e0 * T_TOK + p0] = 2 * t;
        int p1 = atomicAdd(&g_cnt[e1], 1);
        g_list[e1 * T_TOK + p1] = 2 * t + 1;
    }
}

// ======================= GEMM1: H = silu(x@w1) * (x@w3) =======================
// CTA 128x128, 8 warps (2m x 4n), warp 64x32. 4-stage cp.async (A+B1+B3 in smem),
// register double-buffered fragments (load kk+1 while MMA kk).
__global__ void __launch_bounds__(256, 1) gemm1_kernel(const float* __restrict__ xr,
                                                       const float* __restrict__ w1,
                                                       const float* __restrict__ w3) {
    int e   = blockIdx.z;
    int n_e = g_cnt[e];
    int m0  = blockIdx.x * 128;
    if (m0 >= n_e) return;
    int f0  = blockIdx.y * 128;

    extern __shared__ char smem[];
    int* slots = (int*)smem;
    uint32_t sb = smem_u32(smem);
    int tid = threadIdx.x, wid = tid >> 5, lane = tid & 31;

    if (tid < 128) {
        int m = m0 + tid;
        slots[tid] = g_list[e * T_TOK + (m < n_e ? m : m0)];
    }
    __syncthreads();

    const float* W1 = w1 + (size_t)e * D_DIM * F_DIM + f0;
    const float* W3 = w3 + (size_t)e * D_DIM * F_DIM + f0;

    const int STG = A_BYTES + 2 * B_BYTES;   // 53248

    // ---- cp.async producer: chunk ci -> stage s (A + B1 + B3, one commit) ----
    auto issue = [&](int ci, int s) {
        int k0 = ci * 32;
        uint32_t base = sb + 1024 + s * STG;
#pragma unroll
        for (int it = 0; it < 4; it++) {               // A: 128 rows x 8 quads
            int idx = it * 256 + tid;
            int row = idx >> 3, kq = idx & 7;
            const float* src = xr + (size_t)(slots[row] >> 1) * D_DIM + k0 + kq * 4;
            CP16(base + row * 144 + kq * 16, src);
        }
        uint32_t b1b = base + A_BYTES, b3b = base + A_BYTES + B_BYTES;
#pragma unroll
        for (int it = 0; it < 4; it++) {               // B: 32 k-rows x 32 quads
            int idx = it * 256 + tid;
            int kr = idx >> 5, nq = idx & 31;
            size_t off = (size_t)(k0 + kr) * F_DIM + nq * 4;
            CP16(b1b + kr * 544 + nq * 16, W1 + off);
            CP16(b3b + kr * 544 + nq * 16, W3 + off);
        }
        CP_COMMIT();
    };

    issue(0, 0);
    issue(1, 1);
    issue(2, 2);

    int g = lane >> 2, t = lane & 3;
    int m0w = (wid & 1) * 64, n0w = (wid >> 1) * 32;

    float c1[4][4][4], c3[4][4][4];
#pragma unroll
    for (int a = 0; a < 4; a++)
#pragma unroll
        for (int b = 0; b < 4; b++)
#pragma unroll
            for (int r = 0; r < 4; r++) { c1[a][b][r] = 0.f; c3[a][b][r] = 0.f; }

    uint32_t af[2][4][4], b1f[2][4][2], b3f[2][4][2];

    const int NCH = D_DIM / 32;  // 32
    int cur = 0, ibuf = 3;
    for (int ci = 0; ci < NCH; ci++) {
        CP_WAIT2();
        __syncthreads();
        if (ci + 3 < NCH) issue(ci + 3, ibuf); else CP_COMMIT();
        ibuf = (ibuf + 1) & 3;

        const float* As  = (const float*)(smem + 1024 + cur * STG);
        const float* B1s = As + A_BYTES / 4;
        const float* B3s = As + (A_BYTES + B_BYTES) / 4;
        cur = (cur + 1) & 3;

        // fragment loader for k-block kk of this chunk into buffer buf
        auto loadFrag = [&](int kk, int buf) {
#pragma unroll
            for (int mf = 0; mf < 4; mf++) {
                const float* ap = As + (m0w + mf * 16 + g) * AST + kk * 8 + t;
                af[buf][mf][0] = __float_as_uint(ap[0]);
                af[buf][mf][1] = __float_as_uint(ap[8 * AST]);
                af[buf][mf][2] = __float_as_uint(ap[4]);
                af[buf][mf][3] = __float_as_uint(ap[8 * AST + 4]);
            }
#pragma unroll
            for (int nf = 0; nf < 4; nf++) {
                const float* bp = B1s + (kk * 8 + t) * BST + n0w + nf * 8 + g;
                b1f[buf][nf][0] = __float_as_uint(bp[0]);
                b1f[buf][nf][1] = __float_as_uint(bp[4 * BST]);
                const float* cp = B3s + (kk * 8 + t) * BST + n0w + nf * 8 + g;
                b3f[buf][nf][0] = __float_as_uint(cp[0]);
                b3f[buf][nf][1] = __float_as_uint(cp[4 * BST]);
            }
        };

        loadFrag(0, 0);
#pragma unroll
        for (int kk = 0; kk < 4; kk++) {
            if (kk < 3) loadFrag(kk + 1, (kk + 1) & 1);
            int cb = kk & 1;
#pragma unroll
            for (int mf = 0; mf < 4; mf++)
#pragma unroll
                for (int nf = 0; nf < 4; nf++) {
                    MMA_TF32(c1[mf][nf], af[cb][mf], b1f[cb][nf]);
                    MMA_TF32(c3[mf][nf], af[cb][mf], b3f[cb][nf]);
                }
        }
    }

    // ---- epilogue: H = rna_tf32(silu(c1) * c3) ----
#pragma unroll
    for (int mf = 0; mf < 4; mf++) {
#pragma unroll
        for (int half = 0; half < 2; half++) {
            int row = m0w + mf * 16 + g + 8 * half;
            if (m0 + row >= n_e) continue;
            float* hp = g_H + (size_t)slots[row] * F_DIM + f0;
#pragma unroll
            for (int nf = 0; nf < 4; nf++) {
                float v0 = c1[mf][nf][2 * half + 0];
                float v1 = c1[mf][nf][2 * half + 1];
                float2 o;
                o.x = to_tf32((v0 / (1.f + __expf(-v0))) * c3[mf][nf][2 * half + 0]);
                o.y = to_tf32((v1 / (1.f + __expf(-v1))) * c3[mf][nf][2 * half + 1]);
                *(float2*)(hp + n0w + nf * 8 + 2 * t) = o;
            }
        }
    }
}

// ======================= GEMM2: Y = H @ w2 =======================
// 3-stage cp.async, 2 CTAs/SM, B-fragment double buffering (regs <= 128).
__global__ void __launch_bounds__(256, 2) gemm2_kernel(const float* __restrict__ w2) {
    int e   = blockIdx.z;
    int n_e = g_cnt[e];
    int m0  = blockIdx.x * 128;
    if (m0 >= n_e) return;
    int n0  = blockIdx.y * 128;

    extern __shared__ char smem[];
    int* slots = (int*)smem;
    uint32_t sb = smem_u32(smem);
    int tid = threadIdx.x, wid = tid >> 5, lane = tid & 31;

    if (tid < 128) {
        int m = m0 + tid;
        slots[tid] = g_list[e * T_TOK + (m < n_e ? m : m0)];
    }
    __syncthreads();

    const float* W2 = w2 + (size_t)e * F_DIM * D_DIM + n0;
    const int STG = A_BYTES + B_BYTES;   // 35840

    auto issue = [&](int ci, int s) {
        int k0 = ci * 32;
        uint32_t base = sb + 1024 + s * STG;
#pragma unroll
        for (int it = 0; it < 4; it++) {
            int idx = it * 256 + tid;
            int row = idx >> 3, kq = idx & 7;
            const float* src = g_H + (size_t)slots[row] * F_DIM + k0 + kq * 4;
            CP16(base + row * 144 + kq * 16, src);
        }
        uint32_t bb = base + A_BYTES;
#pragma unroll
        for (int it = 0; it < 4; it++) {
            int idx = it * 256 + tid;
            int kr = idx >> 5, nq = idx & 31;
            CP16(bb + kr * 544 + nq * 16, W2 + (size_t)(k0 + kr) * D_DIM + nq * 4);
        }
        CP_COMMIT();
    };

    issue(0, 0);
    issue(1, 1);

    int g = lane >> 2, t = lane & 3;
    int m0w = (wid & 1) * 64, n0w = (wid >> 1) * 32;

    float c[4][4][4];
#pragma unroll
    for (int a = 0; a < 4; a++)
#pragma unroll
        for (int b = 0; b < 4; b++)
#pragma unroll
            for (int r = 0; r < 4; r++) c[a][b][r] = 0.f;

    uint32_t bf[2][4][2];

    const int NCH = F_DIM / 32;  // 64
    int cur = 0, ibuf = 2;
    for (int ci = 0; ci < NCH; ci++) {
        CP_WAIT1();
        __syncthreads();
        if (ci + 2 < NCH) issue(ci + 2, ibuf); else CP_COMMIT();
        if (++ibuf == 3) ibuf = 0;

        const float* As = (const float*)(smem + 1024 + cur * STG);
        const float* Bs = As + A_BYTES / 4;
        if (++cur == 3) cur = 0;

        auto loadB = [&](int kk, int buf) {
#pragma unroll
            for (int nf = 0; nf < 4; nf++) {
                const float* bp = Bs + (kk * 8 + t) * BST + n0w + nf * 8 + g;
                bf[buf][nf][0] = __float_as_uint(bp[0]);
                bf[buf][nf][1] = __float_as_uint(bp[4 * BST]);
            }
        };

        loadB(0, 0);
#pragma unroll
        for (int kk = 0; kk < 4; kk++) {
            if (kk < 3) loadB(kk + 1, (kk + 1) & 1);

            uint32_t af[4][4];
#pragma unroll
            for (int mf = 0; mf < 4; mf++) {
                const float* ap = As + (m0w + mf * 16 + g) * AST + kk * 8 + t;
                af[mf][0] = __float_as_uint(ap[0]);
                af[mf][1] = __float_as_uint(ap[8 * AST]);
                af[mf][2] = __float_as_uint(ap[4]);
                af[mf][3] = __float_as_uint(ap[8 * AST + 4]);
            }
            int cb = kk & 1;
#pragma unroll
            for (int mf = 0; mf < 4; mf++)
#pragma unroll
                for (int nf = 0; nf < 4; nf++)
                    MMA_TF32(c[mf][nf], af[mf], bf[cb][nf]);
        }
    }

#pragma unroll
    for (int mf = 0; mf < 4; mf++) {
#pragma unroll
        for (int half = 0; half < 2; half++) {
            int row = m0w + mf * 16 + g + 8 * half;
            if (m0 + row >= n_e) continue;
            float* yp = g_Y + (size_t)slots[row] * D_DIM + n0;
#pragma unroll
            for (int nf = 0; nf < 4; nf++) {
                float2 o;
                o.x = c[mf][nf][2 * half + 0];
                o.y = c[mf][nf][2 * half + 1];
                *(float2*)(yp + n0w + nf * 8 + 2 * t) = o;
            }
        }
    }
}

// ---------------- combine ----------------
__global__ void __launch_bounds__(256) combine_kernel(float* __restrict__ out) {
    int idx = blockIdx.x * 256 + threadIdx.x;
    int t   = idx / (D_DIM / 4);
    int d4  = idx % (D_DIM / 4);
    float p0 = g_probs[2 * t], p1 = g_probs[2 * t + 1];
    const float4* y0 = (const float4*)(g_Y + (size_t)(2 * t) * D_DIM) + d4;
    const float4* y1 = (const float4*)(g_Y + (size_t)(2 * t + 1) * D_DIM) + d4;
    float4 a = *y0, b = *y1, o;
    o.x = p0 * a.x + p1 * b.x;
    o.y = p0 * a.y + p1 * b.y;
    o.z = p0 * a.z + p1 * b.z;
    o.w = p0 * a.w + p1 * b.w;
    *((float4*)(out + (size_t)t * D_DIM) + d4) = o;
}

// ---------------- launch ----------------
extern "C" void kernel_launch(void* const* d_in, const int* in_sizes, int n_in,
                              void* d_out, int out_size) {
    const float* x  = (const float*)d_in[0];
    const float* wg = (const float*)d_in[1];
    const float* w1 = (const float*)d_in[2];
    const float* w3 = (const float*)d_in[3];
    const float* w2 = (const float*)d_in[4];
    float* out = (float*)d_out;

    const int SMEM1 = 1024 + 4 * (A_BYTES + 2 * B_BYTES);  // 214016
    const int SMEM2 = 1024 + 3 * (A_BYTES + B_BYTES);      // 108544
    cudaFuncSetAttribute(gemm1_kernel, cudaFuncAttributeMaxDynamicSharedMemorySize, SMEM1);
    cudaFuncSetAttribute(gemm2_kernel, cudaFuncAttributeMaxDynamicSharedMemorySize, SMEM2);

    float *xr, *w1r, *w3r, *w2r;
    cudaGetSymbolAddress((void**)&xr,  g_xr);
    cudaGetSymbolAddress((void**)&w1r, g_w1r);
    cudaGetSymbolAddress((void**)&w3r, g_w3r);
    cudaGetSymbolAddress((void**)&w2r, g_w2r);

    init_kernel<<<1, 32>>>();
    round_all_kernel<<<8192, 256>>>((const float4*)x, (const float4*)w1,
                                    (const float4*)w3, (const float4*)w2,
                                    (float4*)xr, (float4*)w1r, (float4*)w3r, (float4*)w2r);
    gate_kernel<<<T_TOK / 8, 256>>>(x, wg);

    gemm1_kernel<<<dim3(T_TOK / 128, F_DIM / 128, E_EXP), 256, SMEM1>>>(xr, w1r, w3r);
    gemm2_kernel<<<dim3(T_TOK / 128, D_DIM / 128, E_EXP), 256, SMEM2>>>(w2r);
    combine_kernel<<<(T_TOK * D_DIM / 4) / 256, 256>>>(out);
}

// round 6
// speedup vs baseline: 1.4779x; 1.4776x over previous
#include <cuda_runtime.h>
#include <cstdint>

#define T_TOK 8192
#define D_DIM 1024
#define E_EXP 8
#define F_DIM 2048
#define NSLOT (2 * T_TOK)

// ---------------- device-global scratch ----------------
__device__ int   g_cnt[E_EXP];
__device__ int   g_list[E_EXP * T_TOK];
__device__ float g_probs[NSLOT];
__device__ float g_H[(size_t)NSLOT * F_DIM];   // tf32-rounded intermediate
__device__ float g_Y[(size_t)NSLOT * D_DIM];

// ---------------- helpers ----------------
__device__ __forceinline__ uint32_t smem_u32(const void* p) {
    uint32_t a;
    asm("{ .reg .u64 t; cvta.to.shared.u64 t, %1; cvt.u32.u64 %0, t; }" : "=r"(a) : "l"(p));
    return a;
}
__device__ __forceinline__ float to_tf32(float x) {
    uint32_t r;
    asm("cvt.rna.tf32.f32 %0, %1;" : "=r"(r) : "f"(x));
    return __uint_as_float(r);
}
// load smem float and round to tf32 in one step (in-place, no extra regs)
__device__ __forceinline__ uint32_t lds_tf32(const float* p) {
    uint32_t r;
    asm("cvt.rna.tf32.f32 %0, %1;" : "=r"(r) : "f"(*p));
    return r;
}
#define CP16(dst, src) asm volatile("cp.async.cg.shared.global [%0], [%1], 16;" :: "r"(dst), "l"(src))
#define CP_COMMIT()    asm volatile("cp.async.commit_group;")
#define CP_WAIT1()     asm volatile("cp.async.wait_group 1;")

#define MMA_TF32(c, a, b)                                                          \
    asm volatile("mma.sync.aligned.m16n8k8.row.col.f32.tf32.tf32.f32 "             \
                 "{%0,%1,%2,%3}, {%4,%5,%6,%7}, {%8,%9}, {%0,%1,%2,%3};"           \
                 : "+f"((c)[0]), "+f"((c)[1]), "+f"((c)[2]), "+f"((c)[3])          \
                 : "r"((a)[0]), "r"((a)[1]), "r"((a)[2]), "r"((a)[3]),             \
                   "r"((b)[0]), "r"((b)[1]))

// smem strides (floats): A rows padded to 36 (144B), B rows padded to 136 (544B)
#define AST 36
#define BST 136
#define A_BYTES (128 * AST * 4)   // 18432
#define B_BYTES (32 * BST * 4)    // 17408

// ---------------- init ----------------
__global__ void init_kernel() {
    if (threadIdx.x < E_EXP) g_cnt[threadIdx.x] = 0;
}

// ---------------- gating (proven) ----------------
__global__ void __launch_bounds__(256) gate_kernel(const float* __restrict__ x,
                                                   const float* __restrict__ wg) {
    __shared__ float swg[E_EXP][D_DIM];
    int tid = threadIdx.x;
    for (int i = tid; i < D_DIM * E_EXP; i += 256) {
        int d = i >> 3, e = i & 7;
        swg[e][d] = wg[i];
    }
    __syncthreads();

    int warp = tid >> 5, lane = tid & 31;
    int t = blockIdx.x * 8 + warp;
    const float* xr = x + (size_t)t * D_DIM;

    float acc[E_EXP];
#pragma unroll
    for (int e = 0; e < E_EXP; e++) acc[e] = 0.f;
    for (int d = lane; d < D_DIM; d += 32) {
        float xv = xr[d];
#pragma unroll
        for (int e = 0; e < E_EXP; e++) acc[e] = fmaf(xv, swg[e][d], acc[e]);
    }
#pragma unroll
    for (int e = 0; e < E_EXP; e++)
#pragma unroll
        for (int o = 16; o > 0; o >>= 1)
            acc[e] += __shfl_xor_sync(0xffffffffu, acc[e], o);

    if (lane == 0) {
        int e0 = 0; float l0 = acc[0];
#pragma unroll
        for (int e = 1; e < E_EXP; e++) if (acc[e] > l0) { l0 = acc[e]; e0 = e; }
        int e1 = -1; float l1 = -3.0e38f;
#pragma unroll
        for (int e = 0; e < E_EXP; e++) {
            if (e == e0) continue;
            if (acc[e] > l1) { l1 = acc[e]; e1 = e; }
        }
        float ex  = __expf(l1 - l0);
        float inv = 1.f / (1.f + ex);
        g_probs[2 * t]     = inv;
        g_probs[2 * t + 1] = ex * inv;
        int p0 = atomicAdd(&g_cnt[e0], 1);
        g_list[e0 * T_TOK + p0] = 2 * t;
        int p1 = atomicAdd(&g_cnt[e1], 1);
        g_list[e1 * T_TOK + p1] = 2 * t + 1;
    }
}

// ======================= GEMM1: H = silu(x@w1) * (x@w3) =======================
// R3-proven structure: CTA 128x128, 8 warps (2m x 4n), warp 64x32, 3-stage
// cp.async. Raw fp32 streamed in; fragments rounded to tf32 (RNA) at LDS time.
__global__ void __launch_bounds__(256, 1) gemm1_kernel(const float* __restrict__ x,
                                                       const float* __restrict__ w1,
                                                       const float* __restrict__ w3) {
    int e   = blockIdx.z;
    int n_e = g_cnt[e];
    int m0  = blockIdx.x * 128;
    if (m0 >= n_e) return;
    int f0  = blockIdx.y * 128;

    extern __shared__ char smem[];
    int* slots = (int*)smem;
    uint32_t sb = smem_u32(smem);
    int tid = threadIdx.x, wid = tid >> 5, lane = tid & 31;

    if (tid < 128) {
        int m = m0 + tid;
        slots[tid] = g_list[e * T_TOK + (m < n_e ? m : m0)];
    }
    __syncthreads();

    const float* W1 = w1 + (size_t)e * D_DIM * F_DIM + f0;
    const float* W3 = w3 + (size_t)e * D_DIM * F_DIM + f0;

    auto issue = [&](int ci, int s) {
        int k0 = ci * 32;
        uint32_t base = sb + 1024 + s * (A_BYTES + 2 * B_BYTES);
#pragma unroll
        for (int it = 0; it < 4; it++) {               // A: 128 rows x 8 quads
            int idx = it * 256 + tid;
            int row = idx >> 3, kq = idx & 7;
            const float* src = x + (size_t)(slots[row] >> 1) * D_DIM + k0 + kq * 4;
            CP16(base + row * 144 + kq * 16, src);
        }
        uint32_t b1b = base + A_BYTES, b3b = base + A_BYTES + B_BYTES;
#pragma unroll
        for (int it = 0; it < 4; it++) {               // B: 32 k-rows x 32 quads
            int idx = it * 256 + tid;
            int kr = idx >> 5, nq = idx & 31;
            size_t off = (size_t)(k0 + kr) * F_DIM + nq * 4;
            CP16(b1b + kr * 544 + nq * 16, W1 + off);
            CP16(b3b + kr * 544 + nq * 16, W3 + off);
        }
        CP_COMMIT();
    };

    issue(0, 0);
    issue(1, 1);

    int g = lane >> 2, t = lane & 3;
    int m0w = (wid & 1) * 64, n0w = (wid >> 1) * 32;

    float c1[4][4][4], c3[4][4][4];
#pragma unroll
    for (int a = 0; a < 4; a++)
#pragma unroll
        for (int b = 0; b < 4; b++)
#pragma unroll
            for (int r = 0; r < 4; r++) { c1[a][b][r] = 0.f; c3[a][b][r] = 0.f; }

    const int NCH = D_DIM / 32;  // 32
    int cur = 0, ibuf = 2;
    for (int ci = 0; ci < NCH; ci++) {
        CP_WAIT1();
        __syncthreads();
        if (ci + 2 < NCH) issue(ci + 2, ibuf); else CP_COMMIT();
        if (++ibuf == 3) ibuf = 0;

        const float* As  = (const float*)(smem + 1024 + cur * (A_BYTES + 2 * B_BYTES));
        const float* B1s = As + A_BYTES / 4;
        const float* B3s = As + (A_BYTES + B_BYTES) / 4;
        if (++cur == 3) cur = 0;

#pragma unroll
        for (int kk = 0; kk < 4; kk++) {
            uint32_t af[4][4], b1f[4][2], b3f[4][2];
#pragma unroll
            for (int mf = 0; mf < 4; mf++) {
                const float* ap = As + (m0w + mf * 16 + g) * AST + kk * 8 + t;
                af[mf][0] = lds_tf32(ap);
                af[mf][1] = lds_tf32(ap + 8 * AST);
                af[mf][2] = lds_tf32(ap + 4);
                af[mf][3] = lds_tf32(ap + 8 * AST + 4);
            }
#pragma unroll
            for (int nf = 0; nf < 4; nf++) {
                const float* bp = B1s + (kk * 8 + t) * BST + n0w + nf * 8 + g;
                b1f[nf][0] = lds_tf32(bp);
                b1f[nf][1] = lds_tf32(bp + 4 * BST);
                const float* cp = B3s + (kk * 8 + t) * BST + n0w + nf * 8 + g;
                b3f[nf][0] = lds_tf32(cp);
                b3f[nf][1] = lds_tf32(cp + 4 * BST);
            }
#pragma unroll
            for (int mf = 0; mf < 4; mf++)
#pragma unroll
                for (int nf = 0; nf < 4; nf++) {
                    MMA_TF32(c1[mf][nf], af[mf], b1f[nf]);
                    MMA_TF32(c3[mf][nf], af[mf], b3f[nf]);
                }
        }
    }

    // ---- epilogue: H = rna_tf32(silu(c1) * c3) ----
#pragma unroll
    for (int mf = 0; mf < 4; mf++) {
#pragma unroll
        for (int half = 0; half < 2; half++) {
            int row = m0w + mf * 16 + g + 8 * half;
            if (m0 + row >= n_e) continue;
            float* hp = g_H + (size_t)slots[row] * F_DIM + f0;
#pragma unroll
            for (int nf = 0; nf < 4; nf++) {
                float v0 = c1[mf][nf][2 * half + 0];
                float v1 = c1[mf][nf][2 * half + 1];
                float2 o;
                o.x = to_tf32((v0 / (1.f + __expf(-v0))) * c3[mf][nf][2 * half + 0]);
                o.y = to_tf32((v1 / (1.f + __expf(-v1))) * c3[mf][nf][2 * half + 1]);
                *(float2*)(hp + n0w + nf * 8 + 2 * t) = o;
            }
        }
    }
}

// ======================= GEMM2: Y = H @ w2 =======================
// R3-proven structure: 3-stage cp.async, 2 CTAs/SM, NO extra register state.
// A (g_H) already tf32-rounded; only B fragments get RNA cvt at LDS time.
__global__ void __launch_bounds__(256, 2) gemm2_kernel(const float* __restrict__ w2) {
    int e   = blockIdx.z;
    int n_e = g_cnt[e];
    int m0  = blockIdx.x * 128;
    if (m0 >= n_e) return;
    int n0  = blockIdx.y * 128;

    extern __shared__ char smem[];
    int* slots = (int*)smem;
    uint32_t sb = smem_u32(smem);
    int tid = threadIdx.x, wid = tid >> 5, lane = tid & 31;

    if (tid < 128) {
        int m = m0 + tid;
        slots[tid] = g_list[e * T_TOK + (m < n_e ? m : m0)];
    }
    __syncthreads();

    const float* W2 = w2 + (size_t)e * F_DIM * D_DIM + n0;

    auto issue = [&](int ci, int s) {
        int k0 = ci * 32;
        uint32_t base = sb + 1024 + s * (A_BYTES + B_BYTES);
#pragma unroll
        for (int it = 0; it < 4; it++) {
            int idx = it * 256 + tid;
            int row = idx >> 3, kq = idx & 7;
            const float* src = g_H + (size_t)slots[row] * F_DIM + k0 + kq * 4;
            CP16(base + row * 144 + kq * 16, src);
        }
        uint32_t bb = base + A_BYTES;
#pragma unroll
        for (int it = 0; it < 4; it++) {
            int idx = it * 256 + tid;
            int kr = idx >> 5, nq = idx & 31;
            CP16(bb + kr * 544 + nq * 16, W2 + (size_t)(k0 + kr) * D_DIM + nq * 4);
        }
        CP_COMMIT();
    };

    issue(0, 0);
    issue(1, 1);

    int g = lane >> 2, t = lane & 3;
    int m0w = (wid & 1) * 64, n0w = (wid >> 1) * 32;

    float c[4][4][4];
#pragma unroll
    for (int a = 0; a < 4; a++)
#pragma unroll
        for (int b = 0; b < 4; b++)
#pragma unroll
            for (int r = 0; r < 4; r++) c[a][b][r] = 0.f;

    const int NCH = F_DIM / 32;  // 64
    int cur = 0, ibuf = 2;
    for (int ci = 0; ci < NCH; ci++) {
        CP_WAIT1();
        __syncthreads();
        if (ci + 2 < NCH) issue(ci + 2, ibuf); else CP_COMMIT();
        if (++ibuf == 3) ibuf = 0;

        const float* As = (const float*)(smem + 1024 + cur * (A_BYTES + B_BYTES));
        const float* Bs = As + A_BYTES / 4;
        if (++cur == 3) cur = 0;

#pragma unroll
        for (int kk = 0; kk < 4; kk++) {
            uint32_t af[4][4], bf[4][2];
#pragma unroll
            for (int mf = 0; mf < 4; mf++) {
                const float* ap = As + (m0w + mf * 16 + g) * AST + kk * 8 + t;
                af[mf][0] = __float_as_uint(ap[0]);
                af[mf][1] = __float_as_uint(ap[8 * AST]);
                af[mf][2] = __float_as_uint(ap[4]);
                af[mf][3] = __float_as_uint(ap[8 * AST + 4]);
            }
#pragma unroll
            for (int nf = 0; nf < 4; nf++) {
                const float* bp = Bs + (kk * 8 + t) * BST + n0w + nf * 8 + g;
                bf[nf][0] = lds_tf32(bp);
                bf[nf][1] = lds_tf32(bp + 4 * BST);
            }
#pragma unroll
            for (int mf = 0; mf < 4; mf++)
#pragma unroll
                for (int nf = 0; nf < 4; nf++)
                    MMA_TF32(c[mf][nf], af[mf], bf[nf]);
        }
    }

#pragma unroll
    for (int mf = 0; mf < 4; mf++) {
#pragma unroll
        for (int half = 0; half < 2; half++) {
            int row = m0w + mf * 16 + g + 8 * half;
            if (m0 + row >= n_e) continue;
            float* yp = g_Y + (size_t)slots[row] * D_DIM + n0;
#pragma unroll
            for (int nf = 0; nf < 4; nf++) {
                float2 o;
                o.x = c[mf][nf][2 * half + 0];
                o.y = c[mf][nf][2 * half + 1];
                *(float2*)(yp + n0w + nf * 8 + 2 * t) = o;
            }
        }
    }
}

// ---------------- combine ----------------
__global__ void __launch_bounds__(256) combine_kernel(float* __restrict__ out) {
    int idx = blockIdx.x * 256 + threadIdx.x;
    int t   = idx / (D_DIM / 4);
    int d4  = idx % (D_DIM / 4);
    float p0 = g_probs[2 * t], p1 = g_probs[2 * t + 1];
    const float4* y0 = (const float4*)(g_Y + (size_t)(2 * t) * D_DIM) + d4;
    const float4* y1 = (const float4*)(g_Y + (size_t)(2 * t + 1) * D_DIM) + d4;
    float4 a = *y0, b = *y1, o;
    o.x = p0 * a.x + p1 * b.x;
    o.y = p0 * a.y + p1 * b.y;
    o.z = p0 * a.z + p1 * b.z;
    o.w = p0 * a.w + p1 * b.w;
    *((float4*)(out + (size_t)t * D_DIM) + d4) = o;
}

// ---------------- launch ----------------
extern "C" void kernel_launch(void* const* d_in, const int* in_sizes, int n_in,
                              void* d_out, int out_size) {
    const float* x  = (const float*)d_in[0];
    const float* wg = (const float*)d_in[1];
    const float* w1 = (const float*)d_in[2];
    const float* w3 = (const float*)d_in[3];
    const float* w2 = (const float*)d_in[4];
    float* out = (float*)d_out;

    const int SMEM1 = 1024 + 3 * (A_BYTES + 2 * B_BYTES);  // 160768
    const int SMEM2 = 1024 + 3 * (A_BYTES + B_BYTES);      // 108544
    cudaFuncSetAttribute(gemm1_kernel, cudaFuncAttributeMaxDynamicSharedMemorySize, SMEM1);
    cudaFuncSetAttribute(gemm2_kernel, cudaFuncAttributeMaxDynamicSharedMemorySize, SMEM2);

    init_kernel<<<1, 32>>>();
    gate_kernel<<<T_TOK / 8, 256>>>(x, wg);
    gemm1_kernel<<<dim3(T_TOK / 128, F_DIM / 128, E_EXP), 256, SMEM1>>>(x, w1, w3);
    gemm2_kernel<<<dim3(T_TOK / 128, D_DIM / 128, E_EXP), 256, SMEM2>>>(w2);
    combine_kernel<<<(T_TOK * D_DIM / 4) / 256, 256>>>(out);
}